// round 11
// baseline (speedup 1.0000x reference)
#include <cuda_runtime.h>
#include <cuda_fp16.h>
#include <cstdint>
#include <math.h>

// Problem constants
#define BATCH 8
#define SEQ   2048
#define FDIM  128
#define WDIM  64
#define MROWS (BATCH * SEQ)   // 16384

#define LOG2E 1.44269504088896f

// Scratch (device globals: allocation-free rule)
// Qh/Ql hold Q * log2(e) split hi/lo (softmax uses ex2 directly).
__device__ __half g_Qh[MROWS * WDIM];
__device__ __half g_Ql[MROWS * WDIM];
__device__ __half g_Kh[MROWS * WDIM];
__device__ __half g_Kl[MROWS * WDIM];
__device__ __half g_Vh[MROWS * FDIM];

// ---------------------------------------------------------------------------
// PTX helpers (baseline ISA: ldmatrix sm_75+, mma sm_80+, cp.async sm_80+)
// ---------------------------------------------------------------------------
__device__ __forceinline__ uint32_t cvta_s(const void* p) {
    uint32_t a;
    asm("{ .reg .u64 t; cvta.to.shared.u64 t, %1; cvt.u32.u64 %0, t; }"
        : "=r"(a) : "l"(p));
    return a;
}
__device__ __forceinline__ void ldsm4(uint32_t addr, uint32_t& r0, uint32_t& r1,
                                      uint32_t& r2, uint32_t& r3) {
    asm volatile("ldmatrix.sync.aligned.m8n8.x4.shared.b16 {%0,%1,%2,%3}, [%4];"
                 : "=r"(r0), "=r"(r1), "=r"(r2), "=r"(r3) : "r"(addr));
}
__device__ __forceinline__ void ldsm4t(uint32_t addr, uint32_t& r0, uint32_t& r1,
                                       uint32_t& r2, uint32_t& r3) {
    asm volatile("ldmatrix.sync.aligned.m8n8.x4.trans.shared.b16 {%0,%1,%2,%3}, [%4];"
                 : "=r"(r0), "=r"(r1), "=r"(r2), "=r"(r3) : "r"(addr));
}
__device__ __forceinline__ void mma_f16(float* c, uint32_t a0, uint32_t a1,
                                        uint32_t a2, uint32_t a3,
                                        uint32_t b0, uint32_t b1) {
    asm volatile(
        "mma.sync.aligned.m16n8k16.row.col.f32.f16.f16.f32 "
        "{%0,%1,%2,%3}, {%4,%5,%6,%7}, {%8,%9}, {%0,%1,%2,%3};"
        : "+f"(c[0]), "+f"(c[1]), "+f"(c[2]), "+f"(c[3])
        : "r"(a0), "r"(a1), "r"(a2), "r"(a3), "r"(b0), "r"(b1));
}
__device__ __forceinline__ void cpa16(uint32_t d, const void* s) {
    asm volatile("cp.async.cg.shared.global [%0], [%1], 16;" :: "r"(d), "l"(s));
}
#define CP_COMMIT() asm volatile("cp.async.commit_group;" ::: "memory")
#define CP_WAIT1()  asm volatile("cp.async.wait_group 1;" ::: "memory")
#define CP_WAIT0()  asm volatile("cp.async.wait_group 0;" ::: "memory")

__device__ __forceinline__ float ex2(float x) {
    float y;
    asm("ex2.approx.ftz.f32 %0, %1;" : "=f"(y) : "f"(x));
    return y;
}

// ---------------------------------------------------------------------------
// Attention SMEM layout (bytes). Padded strides keep ldmatrix conflict-free.
// CTA = 64 q-rows, 128 threads (4 warps x 16 rows); KV tiles of 64,
// double-buffered. smem = 90112 B, 255 regs -> 2 CTAs/SM so co-resident
// CTAs desynchronize and fill each other's tensor-pipe bubbles.
// ---------------------------------------------------------------------------
#define QS 72
#define KS 72
#define VS 136
#define SQH_OFF  0
#define SQL_OFF  (64 * QS * 2)              // 9216
#define STAGE_OFF (2 * 64 * QS * 2)         // 18432
#define KH_OFF   0
#define KL_OFF   (64 * KS * 2)              // 9216
#define SV_OFF   (2 * 64 * KS * 2)          // 18432
#define STAGE_SZ (2 * 64 * KS * 2 + 64 * VS * 2)     // 35840
#define ATTN_SMEM (STAGE_OFF + 2 * STAGE_SZ)         // 90112

__device__ __forceinline__ void stage_load(uint32_t base,
                                           const __half* Khb, const __half* Klb,
                                           const __half* Vhb, int kv0, int tid) {
    #pragma unroll
    for (int i = 0; i < 4; ++i) {
        int c = i * 128 + tid;
        int r = c >> 3, c8 = (c & 7) * 8;
        cpa16(base + KH_OFF + (r * KS + c8) * 2, Khb + (size_t)(kv0 + r) * WDIM + c8);
        cpa16(base + KL_OFF + (r * KS + c8) * 2, Klb + (size_t)(kv0 + r) * WDIM + c8);
    }
    #pragma unroll
    for (int i = 0; i < 8; ++i) {
        int c = i * 128 + tid;
        int r = c >> 4, c8 = (c & 15) * 8;
        cpa16(base + SV_OFF + (r * VS + c8) * 2, Vhb + (size_t)(kv0 + r) * FDIM + c8);
    }
}

// ---------------------------------------------------------------------------
// FA2-style fused attention on mma.sync fp16.
// grid = (SEQ/64, BATCH) = (32, 8) = 256 CTAs, 128 threads.
// Q is pre-scaled by log2(e): softmax uses raw ex2.
// ---------------------------------------------------------------------------
__global__ __launch_bounds__(128, 2) void attn_mma_kernel(
    const __half* __restrict__ Qh, const __half* __restrict__ Ql,
    const __half* __restrict__ Kh, const __half* __restrict__ Kl,
    const __half* __restrict__ Vh, float* __restrict__ out) {
    extern __shared__ char smem[];
    const uint32_t sb = cvta_s(smem);
    const int tid = threadIdx.x;
    const int lane = tid & 31;
    const int g = lane >> 2;
    const int tig = lane & 3;
    const int grp = lane >> 3;
    const int lr = lane & 7;
    const int wbase = (tid >> 5) * 16;   // 4 warps x 16 q-rows = 64

    const int b = blockIdx.y;
    const int q0 = blockIdx.x * 64;
    const __half* Qhb = Qh + ((size_t)b * SEQ + q0) * WDIM;
    const __half* Qlb = Ql + ((size_t)b * SEQ + q0) * WDIM;
    const __half* Khb = Kh + (size_t)b * SEQ * WDIM;
    const __half* Klb = Kl + (size_t)b * SEQ * WDIM;
    const __half* Vhb = Vh + (size_t)b * SEQ * FDIM;
    float* outb = out + ((size_t)b * SEQ + q0) * FDIM;

    // Prologue: Q (group 0), stage 0 (group 1)
    #pragma unroll
    for (int i = 0; i < 4; ++i) {
        int c = i * 128 + tid;
        int r = c >> 3, c8 = (c & 7) * 8;
        cpa16(sb + SQH_OFF + (r * QS + c8) * 2, Qhb + (size_t)r * WDIM + c8);
        cpa16(sb + SQL_OFF + (r * QS + c8) * 2, Qlb + (size_t)r * WDIM + c8);
    }
    CP_COMMIT();
    stage_load(sb + STAGE_OFF, Khb, Klb, Vhb, 0, tid);
    CP_COMMIT();

    CP_WAIT1();
    __syncthreads();
    uint32_t qh[4][4], ql[4][4];
    #pragma unroll
    for (int kk = 0; kk < 4; ++kk) {
        uint32_t a = sb + SQH_OFF +
            ((wbase + lr + (grp & 1) * 8) * QS + kk * 16 + (grp >> 1) * 8) * 2;
        ldsm4(a, qh[kk][0], qh[kk][1], qh[kk][2], qh[kk][3]);
        uint32_t al = a + (SQL_OFF - SQH_OFF);
        ldsm4(al, ql[kk][0], ql[kk][1], ql[kk][2], ql[kk][3]);
    }

    float o[16][4];
    #pragma unroll
    for (int nt = 0; nt < 16; ++nt)
        #pragma unroll
        for (int j = 0; j < 4; ++j) o[nt][j] = 0.0f;
    float m0 = -INFINITY, m1 = -INFINITY, l0 = 0.0f, l1 = 0.0f;

    for (int t = 0; t < SEQ / 64; ++t) {
        if (t + 1 < SEQ / 64) {
            stage_load(sb + STAGE_OFF + ((t + 1) & 1) * STAGE_SZ,
                       Khb, Klb, Vhb, (t + 1) * 64, tid);
            CP_COMMIT();
            CP_WAIT1();
        } else {
            CP_WAIT0();
        }
        __syncthreads();

        const uint32_t stg = sb + STAGE_OFF + (t & 1) * STAGE_SZ;

        // ---- S' = (Q*log2e) K^T over 64 kv cols (3-term compensated) ----
        float c[8][4];
        #pragma unroll
        for (int nt = 0; nt < 8; ++nt)
            #pragma unroll
            for (int j = 0; j < 4; ++j) c[nt][j] = 0.0f;

        #pragma unroll
        for (int kk = 0; kk < 4; ++kk) {
            #pragma unroll
            for (int nn2 = 0; nn2 < 4; ++nn2) {
                uint32_t off = (((nn2 * 2 + (grp >> 1)) * 8 + lr) * KS
                                + kk * 16 + (grp & 1) * 8) * 2;
                uint32_t h0, h1, h2, h3, e0, e1, e2, e3;
                ldsm4(stg + KH_OFF + off, h0, h1, h2, h3);
                ldsm4(stg + KL_OFF + off, e0, e1, e2, e3);
                mma_f16(c[2 * nn2],     qh[kk][0], qh[kk][1], qh[kk][2], qh[kk][3], h0, h1);
                mma_f16(c[2 * nn2 + 1], qh[kk][0], qh[kk][1], qh[kk][2], qh[kk][3], h2, h3);
                mma_f16(c[2 * nn2],     qh[kk][0], qh[kk][1], qh[kk][2], qh[kk][3], e0, e1);
                mma_f16(c[2 * nn2 + 1], qh[kk][0], qh[kk][1], qh[kk][2], qh[kk][3], e2, e3);
                mma_f16(c[2 * nn2],     ql[kk][0], ql[kk][1], ql[kk][2], ql[kk][3], h0, h1);
                mma_f16(c[2 * nn2 + 1], ql[kk][0], ql[kk][1], ql[kk][2], ql[kk][3], h2, h3);
            }
        }

        // ---- Online softmax in registers (base-2) ----
        float mt0 = -INFINITY, mt1 = -INFINITY;
        #pragma unroll
        for (int nt = 0; nt < 8; ++nt) {
            mt0 = fmaxf(mt0, fmaxf(c[nt][0], c[nt][1]));
            mt1 = fmaxf(mt1, fmaxf(c[nt][2], c[nt][3]));
        }
        mt0 = fmaxf(mt0, __shfl_xor_sync(0xffffffffu, mt0, 1));
        mt0 = fmaxf(mt0, __shfl_xor_sync(0xffffffffu, mt0, 2));
        mt1 = fmaxf(mt1, __shfl_xor_sync(0xffffffffu, mt1, 1));
        mt1 = fmaxf(mt1, __shfl_xor_sync(0xffffffffu, mt1, 2));

        const float mn0 = fmaxf(m0, mt0);
        const float mn1 = fmaxf(m1, mt1);
        const float sc0 = ex2(m0 - mn0);   // first tile: ex2(-inf) = 0
        const float sc1 = ex2(m1 - mn1);
        m0 = mn0; m1 = mn1;

        uint32_t p[8][2];
        float lp0 = 0.0f, lp1 = 0.0f;
        #pragma unroll
        for (int nt = 0; nt < 8; ++nt) {
            const float e00 = ex2(c[nt][0] - mn0);
            const float e01 = ex2(c[nt][1] - mn0);
            const float e10 = ex2(c[nt][2] - mn1);
            const float e11 = ex2(c[nt][3] - mn1);
            lp0 += e00 + e01;
            lp1 += e10 + e11;
            __half2 h20 = __floats2half2_rn(e00, e01);
            __half2 h21 = __floats2half2_rn(e10, e11);
            p[nt][0] = *reinterpret_cast<uint32_t*>(&h20);
            p[nt][1] = *reinterpret_cast<uint32_t*>(&h21);
        }
        l0 = l0 * sc0 + lp0;
        l1 = l1 * sc1 + lp1;

        #pragma unroll
        for (int nt = 0; nt < 16; ++nt) {
            o[nt][0] *= sc0; o[nt][1] *= sc0;
            o[nt][2] *= sc1; o[nt][3] *= sc1;
        }

        // ---- O += P @ V (P C-frag reuses directly as A-frag) ----
        #pragma unroll
        for (int kk2 = 0; kk2 < 4; ++kk2) {
            const uint32_t a0 = p[2 * kk2][0];
            const uint32_t a1 = p[2 * kk2][1];
            const uint32_t a2 = p[2 * kk2 + 1][0];
            const uint32_t a3 = p[2 * kk2 + 1][1];
            #pragma unroll
            for (int nn2 = 0; nn2 < 8; ++nn2) {
                uint32_t va = stg + SV_OFF +
                    ((kk2 * 16 + (grp & 1) * 8 + lr) * VS
                     + (nn2 * 2 + (grp >> 1)) * 8) * 2;
                uint32_t v0, v1, v2, v3;
                ldsm4t(va, v0, v1, v2, v3);
                mma_f16(o[2 * nn2],     a0, a1, a2, a3, v0, v1);
                mma_f16(o[2 * nn2 + 1], a0, a1, a2, a3, v2, v3);
            }
        }
        __syncthreads();   // all warps done with this stage buffer
    }

    l0 += __shfl_xor_sync(0xffffffffu, l0, 1);
    l0 += __shfl_xor_sync(0xffffffffu, l0, 2);
    l1 += __shfl_xor_sync(0xffffffffu, l1, 1);
    l1 += __shfl_xor_sync(0xffffffffu, l1, 2);
    const float inv0 = 1.0f / l0;
    const float inv1 = 1.0f / l1;

    #pragma unroll
    for (int nt = 0; nt < 16; ++nt) {
        float2 w0 = make_float2(o[nt][0] * inv0, o[nt][1] * inv0);
        float2 w1 = make_float2(o[nt][2] * inv1, o[nt][3] * inv1);
        *reinterpret_cast<float2*>(&outb[(size_t)(wbase + g) * FDIM + nt * 8 + 2 * tig]) = w0;
        *reinterpret_cast<float2*>(&outb[(size_t)(wbase + g + 8) * FDIM + nt * 8 + 2 * tig]) = w1;
    }
}

// ---------------------------------------------------------------------------
// Tensor-core projections, single pass: x tile split hi/lo ONCE, all three
// weight matrices resident in smem, K/Q/V computed sequentially.
// grid = (MROWS/128, 1). K,Q: 3-term compensated product, hi/lo outputs
// (Q scaled by log2e). V: 2-term (full x, w hi), fp16 output.
// ---------------------------------------------------------------------------
#define PXS 136                                  // half stride (272 B rows)
#define PXH_OFF 0
#define PXL_OFF 34816
#define WKH_OFF 69632
#define WKL_OFF (WKH_OFF + 17408)                // 87040
#define WQH_OFF (WKL_OFF + 17408)                // 104448
#define WQL_OFF (WQH_OFF + 17408)                // 121856
#define WVH_OFF (WQL_OFF + 17408)                // 139264
#define PROJ_SMEM (WVH_OFF + 34816)              // 174080

__global__ __launch_bounds__(256, 1) void proj_mma_kernel(
    const float* __restrict__ x,
    const float* __restrict__ wk,
    const float* __restrict__ wq,
    const float* __restrict__ wv,
    __half* __restrict__ Kh, __half* __restrict__ Kl,
    __half* __restrict__ Qh, __half* __restrict__ Ql,
    __half* __restrict__ Vh) {
    extern __shared__ char ps[];
    const uint32_t sb = cvta_s(ps);
    const int tid = threadIdx.x;
    const int lane = tid & 31;
    const int g = lane >> 2;
    const int tig = lane & 3;
    const int grp = lane >> 3;
    const int lr = lane & 7;
    const int wbase = (tid >> 5) * 16;
    const int row0 = blockIdx.x * 128;

    // Load + split x tile [128][128] fp32 -> hi/lo fp16 (once)
    #pragma unroll
    for (int i = 0; i < 16; ++i) {
        int e = i * 256 + tid;
        int r = e >> 5;
        int c4 = (e & 31) * 4;
        float4 v = *reinterpret_cast<const float4*>(&x[(size_t)(row0 + r) * 128 + c4]);
        __half hx = __float2half_rn(v.x), hy = __float2half_rn(v.y);
        __half hz = __float2half_rn(v.z), hw = __float2half_rn(v.w);
        char* dh = ps + PXH_OFF + ((size_t)r * PXS + c4) * 2;
        char* dl = ps + PXL_OFF + ((size_t)r * PXS + c4) * 2;
        *reinterpret_cast<__half2*>(dh)     = __halves2half2(hx, hy);
        *reinterpret_cast<__half2*>(dh + 4) = __halves2half2(hz, hw);
        *reinterpret_cast<__half2*>(dl) = __halves2half2(
            __float2half_rn(v.x - __half2float(hx)),
            __float2half_rn(v.y - __half2float(hy)));
        *reinterpret_cast<__half2*>(dl + 4) = __halves2half2(
            __float2half_rn(v.z - __half2float(hz)),
            __float2half_rn(v.w - __half2float(hw)));
    }
    // wk, wq transposed + split hi/lo; wv transposed hi only
    #pragma unroll 4
    for (int e = tid; e < 128 * 64; e += 256) {
        int k = e >> 6, n = e & 63;
        float v = wk[(size_t)k * 64 + n];
        __half hi = __float2half_rn(v);
        *reinterpret_cast<__half*>(ps + WKH_OFF + ((size_t)n * PXS + k) * 2) = hi;
        *reinterpret_cast<__half*>(ps + WKL_OFF + ((size_t)n * PXS + k) * 2) =
            __float2half_rn(v - __half2float(hi));
        float vq = wq[(size_t)k * 64 + n];
        __half hq = __float2half_rn(vq);
        *reinterpret_cast<__half*>(ps + WQH_OFF + ((size_t)n * PXS + k) * 2) = hq;
        *reinterpret_cast<__half*>(ps + WQL_OFF + ((size_t)n * PXS + k) * 2) =
            __float2half_rn(vq - __half2float(hq));
    }
    #pragma unroll 8
    for (int e = tid; e < 128 * 128; e += 256) {
        int k = e >> 7, n = e & 127;
        *reinterpret_cast<__half*>(ps + WVH_OFF + ((size_t)n * PXS + k) * 2) =
            __float2half_rn(wv[(size_t)k * 128 + n]);
    }
    __syncthreads();

    // A-frags (x hi/lo), 8 k-steps — held for all three GEMMs
    uint32_t ah[8][4], al[8][4];
    #pragma unroll
    for (int kk = 0; kk < 8; ++kk) {
        uint32_t a = sb + PXH_OFF +
            ((wbase + lr + (grp & 1) * 8) * PXS + kk * 16 + (grp >> 1) * 8) * 2;
        ldsm4(a, ah[kk][0], ah[kk][1], ah[kk][2], ah[kk][3]);
        ldsm4(a + (PXL_OFF - PXH_OFF), al[kk][0], al[kk][1], al[kk][2], al[kk][3]);
    }

    // ---- K and Q: N=64, 3-term compensated product ----
    #pragma unroll
    for (int which = 0; which < 2; ++which) {
        const uint32_t wh_off = (which == 0) ? WKH_OFF : WQH_OFF;
        const uint32_t wl_off = (which == 0) ? WKL_OFF : WQL_OFF;

        float c[8][4];
        #pragma unroll
        for (int nt = 0; nt < 8; ++nt)
            #pragma unroll
            for (int j = 0; j < 4; ++j) c[nt][j] = 0.0f;

        #pragma unroll
        for (int kk = 0; kk < 8; ++kk) {
            #pragma unroll
            for (int nn2 = 0; nn2 < 4; ++nn2) {
                uint32_t off = (((nn2 * 2 + (grp >> 1)) * 8 + lr) * PXS
                                + kk * 16 + (grp & 1) * 8) * 2;
                uint32_t h0, h1, h2, h3, e0, e1, e2, e3;
                ldsm4(sb + wh_off + off, h0, h1, h2, h3);
                ldsm4(sb + wl_off + off, e0, e1, e2, e3);
                mma_f16(c[2 * nn2],     ah[kk][0], ah[kk][1], ah[kk][2], ah[kk][3], h0, h1);
                mma_f16(c[2 * nn2 + 1], ah[kk][0], ah[kk][1], ah[kk][2], ah[kk][3], h2, h3);
                mma_f16(c[2 * nn2],     ah[kk][0], ah[kk][1], ah[kk][2], ah[kk][3], e0, e1);
                mma_f16(c[2 * nn2 + 1], ah[kk][0], ah[kk][1], ah[kk][2], ah[kk][3], e2, e3);
                mma_f16(c[2 * nn2],     al[kk][0], al[kk][1], al[kk][2], al[kk][3], h0, h1);
                mma_f16(c[2 * nn2 + 1], al[kk][0], al[kk][1], al[kk][2], al[kk][3], h2, h3);
            }
        }

        const float scale = (which == 1) ? LOG2E : 1.0f;  // fold log2e into Q
        __half* Hh = (which == 0) ? Kh : Qh;
        __half* Hl = (which == 0) ? Kl : Ql;
        #pragma unroll
        for (int nt = 0; nt < 8; ++nt) {
            const int col = nt * 8 + 2 * tig;
            #pragma unroll
            for (int half_m = 0; half_m < 2; ++half_m) {
                const size_t idx =
                    (size_t)(row0 + wbase + g + half_m * 8) * WDIM + col;
                const float v0 = c[nt][2 * half_m] * scale;
                const float v1 = c[nt][2 * half_m + 1] * scale;
                const __half h0 = __float2half_rn(v0);
                const __half h1 = __float2half_rn(v1);
                *reinterpret_cast<__half2*>(&Hh[idx]) = __halves2half2(h0, h1);
                *reinterpret_cast<__half2*>(&Hl[idx]) = __halves2half2(
                    __float2half_rn(v0 - __half2float(h0)),
                    __float2half_rn(v1 - __half2float(h1)));
            }
        }
    }

    // ---- V: N=128, 2-term (x hi+lo, w hi) ----
    {
        float c[16][4];
        #pragma unroll
        for (int nt = 0; nt < 16; ++nt)
            #pragma unroll
            for (int j = 0; j < 4; ++j) c[nt][j] = 0.0f;

        #pragma unroll
        for (int kk = 0; kk < 8; ++kk) {
            #pragma unroll
            for (int nn2 = 0; nn2 < 8; ++nn2) {
                uint32_t off = (((nn2 * 2 + (grp >> 1)) * 8 + lr) * PXS
                                + kk * 16 + (grp & 1) * 8) * 2;
                uint32_t h0, h1, h2, h3;
                ldsm4(sb + WVH_OFF + off, h0, h1, h2, h3);
                mma_f16(c[2 * nn2],     ah[kk][0], ah[kk][1], ah[kk][2], ah[kk][3], h0, h1);
                mma_f16(c[2 * nn2 + 1], ah[kk][0], ah[kk][1], ah[kk][2], ah[kk][3], h2, h3);
                mma_f16(c[2 * nn2],     al[kk][0], al[kk][1], al[kk][2], al[kk][3], h0, h1);
                mma_f16(c[2 * nn2 + 1], al[kk][0], al[kk][1], al[kk][2], al[kk][3], h2, h3);
            }
        }

        #pragma unroll
        for (int nt = 0; nt < 16; ++nt) {
            const int col = nt * 8 + 2 * tig;
            #pragma unroll
            for (int half_m = 0; half_m < 2; ++half_m) {
                const size_t idx =
                    (size_t)(row0 + wbase + g + half_m * 8) * FDIM + col;
                *reinterpret_cast<__half2*>(&Vh[idx]) = __halves2half2(
                    __float2half_rn(c[nt][2 * half_m]),
                    __float2half_rn(c[nt][2 * half_m + 1]));
            }
        }
    }
}

// ---------------------------------------------------------------------------
extern "C" void kernel_launch(void* const* d_in, const int* in_sizes, int n_in,
                              void* d_out, int out_size) {
    const float* x  = (const float*)d_in[0];
    // d_in[1] = adj (bool), unused by the reference math
    const float* wk = (const float*)d_in[2];
    const float* wv = (const float*)d_in[3];
    const float* wq = (const float*)d_in[4];
    float* out = (float*)d_out;

    void *pQh, *pQl, *pKh, *pKl, *pVh;
    cudaGetSymbolAddress(&pQh, g_Qh);
    cudaGetSymbolAddress(&pQl, g_Ql);
    cudaGetSymbolAddress(&pKh, g_Kh);
    cudaGetSymbolAddress(&pKl, g_Kl);
    cudaGetSymbolAddress(&pVh, g_Vh);

    cudaFuncSetAttribute(attn_mma_kernel,
                         cudaFuncAttributeMaxDynamicSharedMemorySize, ATTN_SMEM);
    cudaFuncSetAttribute(proj_mma_kernel,
                         cudaFuncAttributeMaxDynamicSharedMemorySize, PROJ_SMEM);

    proj_mma_kernel<<<dim3(MROWS / 128, 1), 256, PROJ_SMEM>>>(
        x, wk, wq, wv,
        (__half*)pKh, (__half*)pKl, (__half*)pQh, (__half*)pQl, (__half*)pVh);

    attn_mma_kernel<<<dim3(SEQ / 64, BATCH), 128, ATTN_SMEM>>>(
        (const __half*)pQh, (const __half*)pQl,
        (const __half*)pKh, (const __half*)pKl,
        (const __half*)pVh, out);
}

// round 14
// speedup vs baseline: 1.5260x; 1.5260x over previous
#include <cuda_runtime.h>
#include <cuda_fp16.h>
#include <cstdint>
#include <math.h>

// Problem constants
#define BATCH 8
#define SEQ   2048
#define FDIM  128
#define WDIM  64
#define MROWS (BATCH * SEQ)   // 16384

#define LOG2E 1.44269504088896f

// Scratch (device globals: allocation-free rule)
// Qh/Ql hold Q * log2(e) split hi/lo (softmax uses ex2 directly).
__device__ __half g_Qh[MROWS * WDIM];
__device__ __half g_Ql[MROWS * WDIM];
__device__ __half g_Kh[MROWS * WDIM];
__device__ __half g_Kl[MROWS * WDIM];
__device__ __half g_Vh[MROWS * FDIM];
// Transposed + hi/lo-split weights, produced once by wprep_kernel:
// layout [n][k], row stride 128 halfs.
__device__ __half g_WKh[64 * 128];
__device__ __half g_WKl[64 * 128];
__device__ __half g_WQh[64 * 128];
__device__ __half g_WQl[64 * 128];
__device__ __half g_WVh[128 * 128];

// ---------------------------------------------------------------------------
// PTX helpers (baseline ISA: ldmatrix sm_75+, mma sm_80+, cp.async sm_80+)
// ---------------------------------------------------------------------------
__device__ __forceinline__ uint32_t cvta_s(const void* p) {
    uint32_t a;
    asm("{ .reg .u64 t; cvta.to.shared.u64 t, %1; cvt.u32.u64 %0, t; }"
        : "=r"(a) : "l"(p));
    return a;
}
__device__ __forceinline__ void ldsm4(uint32_t addr, uint32_t& r0, uint32_t& r1,
                                      uint32_t& r2, uint32_t& r3) {
    asm volatile("ldmatrix.sync.aligned.m8n8.x4.shared.b16 {%0,%1,%2,%3}, [%4];"
                 : "=r"(r0), "=r"(r1), "=r"(r2), "=r"(r3) : "r"(addr));
}
__device__ __forceinline__ void ldsm4t(uint32_t addr, uint32_t& r0, uint32_t& r1,
                                       uint32_t& r2, uint32_t& r3) {
    asm volatile("ldmatrix.sync.aligned.m8n8.x4.trans.shared.b16 {%0,%1,%2,%3}, [%4];"
                 : "=r"(r0), "=r"(r1), "=r"(r2), "=r"(r3) : "r"(addr));
}
__device__ __forceinline__ void mma_f16(float* c, uint32_t a0, uint32_t a1,
                                        uint32_t a2, uint32_t a3,
                                        uint32_t b0, uint32_t b1) {
    asm volatile(
        "mma.sync.aligned.m16n8k16.row.col.f32.f16.f16.f32 "
        "{%0,%1,%2,%3}, {%4,%5,%6,%7}, {%8,%9}, {%0,%1,%2,%3};"
        : "+f"(c[0]), "+f"(c[1]), "+f"(c[2]), "+f"(c[3])
        : "r"(a0), "r"(a1), "r"(a2), "r"(a3), "r"(b0), "r"(b1));
}
__device__ __forceinline__ void cpa16(uint32_t d, const void* s) {
    asm volatile("cp.async.cg.shared.global [%0], [%1], 16;" :: "r"(d), "l"(s));
}
#define CP_COMMIT() asm volatile("cp.async.commit_group;" ::: "memory")
#define CP_WAIT1()  asm volatile("cp.async.wait_group 1;" ::: "memory")
#define CP_WAIT0()  asm volatile("cp.async.wait_group 0;" ::: "memory")

__device__ __forceinline__ float ex2(float x) {
    float y;
    asm("ex2.approx.ftz.f32 %0, %1;" : "=f"(y) : "f"(x));
    return y;
}

// ---------------------------------------------------------------------------
// Attention SMEM layout (bytes). Padded strides keep ldmatrix conflict-free:
// row stride 72h=144B / 136h=272B -> 8 rows hit 8 distinct 16B bank groups.
// ---------------------------------------------------------------------------
#define QS 72
#define KS 72
#define VS 136
#define SQH_OFF  0
#define SQL_OFF  (128 * QS * 2)             // 18432
#define STAGE_OFF (2 * 128 * QS * 2)        // 36864
#define KH_OFF   0
#define KL_OFF   (128 * KS * 2)             // 18432
#define SV_OFF   (2 * 128 * KS * 2)         // 36864
#define STAGE_SZ (2 * 128 * KS * 2 + 128 * VS * 2)   // 71680
#define ATTN_SMEM (STAGE_OFF + 2 * STAGE_SZ)         // 180224

__device__ __forceinline__ void stage_load(uint32_t base,
                                           const __half* Khb, const __half* Klb,
                                           const __half* Vhb, int kv0, int tid) {
    #pragma unroll
    for (int i = 0; i < 4; ++i) {
        int c = i * 256 + tid;
        int r = c >> 3, c8 = (c & 7) * 8;
        cpa16(base + KH_OFF + (r * KS + c8) * 2, Khb + (size_t)(kv0 + r) * WDIM + c8);
        cpa16(base + KL_OFF + (r * KS + c8) * 2, Klb + (size_t)(kv0 + r) * WDIM + c8);
    }
    #pragma unroll
    for (int i = 0; i < 8; ++i) {
        int c = i * 256 + tid;
        int r = c >> 4, c8 = (c & 15) * 8;
        cpa16(base + SV_OFF + (r * VS + c8) * 2, Vhb + (size_t)(kv0 + r) * FDIM + c8);
    }
}

// ---------------------------------------------------------------------------
// FA2-style fused attention on mma.sync fp16 (R9 configuration: 128 q-rows,
// 256 threads, KV tile 128 split into two pipelined 64-col halves).
// grid = (SEQ/128, BATCH) = (16, 8). Q pre-scaled by log2(e).
// ---------------------------------------------------------------------------
__global__ __launch_bounds__(256, 1) void attn_mma_kernel(
    const __half* __restrict__ Qh, const __half* __restrict__ Ql,
    const __half* __restrict__ Kh, const __half* __restrict__ Kl,
    const __half* __restrict__ Vh, float* __restrict__ out) {
    extern __shared__ char smem[];
    const uint32_t sb = cvta_s(smem);
    const int tid = threadIdx.x;
    const int lane = tid & 31;
    const int g = lane >> 2;
    const int tig = lane & 3;
    const int grp = lane >> 3;
    const int lr = lane & 7;
    const int wbase = (tid >> 5) * 16;

    const int b = blockIdx.y;
    const int q0 = blockIdx.x * 128;
    const __half* Qhb = Qh + ((size_t)b * SEQ + q0) * WDIM;
    const __half* Qlb = Ql + ((size_t)b * SEQ + q0) * WDIM;
    const __half* Khb = Kh + (size_t)b * SEQ * WDIM;
    const __half* Klb = Kl + (size_t)b * SEQ * WDIM;
    const __half* Vhb = Vh + (size_t)b * SEQ * FDIM;
    float* outb = out + ((size_t)b * SEQ + q0) * FDIM;

    #pragma unroll
    for (int i = 0; i < 4; ++i) {
        int c = i * 256 + tid;
        int r = c >> 3, c8 = (c & 7) * 8;
        cpa16(sb + SQH_OFF + (r * QS + c8) * 2, Qhb + (size_t)r * WDIM + c8);
        cpa16(sb + SQL_OFF + (r * QS + c8) * 2, Qlb + (size_t)r * WDIM + c8);
    }
    CP_COMMIT();
    stage_load(sb + STAGE_OFF, Khb, Klb, Vhb, 0, tid);
    CP_COMMIT();

    CP_WAIT1();
    __syncthreads();
    uint32_t qh[4][4], ql[4][4];
    #pragma unroll
    for (int kk = 0; kk < 4; ++kk) {
        uint32_t a = sb + SQH_OFF +
            ((wbase + lr + (grp & 1) * 8) * QS + kk * 16 + (grp >> 1) * 8) * 2;
        ldsm4(a, qh[kk][0], qh[kk][1], qh[kk][2], qh[kk][3]);
        uint32_t al = a + (SQL_OFF - SQH_OFF);
        ldsm4(al, ql[kk][0], ql[kk][1], ql[kk][2], ql[kk][3]);
    }

    float o[16][4];
    #pragma unroll
    for (int nt = 0; nt < 16; ++nt)
        #pragma unroll
        for (int j = 0; j < 4; ++j) o[nt][j] = 0.0f;
    float m0 = -INFINITY, m1 = -INFINITY, l0 = 0.0f, l1 = 0.0f;

    for (int t = 0; t < 16; ++t) {
        if (t + 1 < 16) {
            stage_load(sb + STAGE_OFF + ((t + 1) & 1) * STAGE_SZ,
                       Khb, Klb, Vhb, (t + 1) * 128, tid);
            CP_COMMIT();
            CP_WAIT1();
        } else {
            CP_WAIT0();
        }
        __syncthreads();

        const uint32_t stg = sb + STAGE_OFF + (t & 1) * STAGE_SZ;

        // ---- QK half A (kv cols 0..63) and half B (64..127) ----
        float ca[8][4], cb[8][4];
        #pragma unroll
        for (int nt = 0; nt < 8; ++nt)
            #pragma unroll
            for (int j = 0; j < 4; ++j) { ca[nt][j] = 0.0f; cb[nt][j] = 0.0f; }

        #pragma unroll
        for (int kk = 0; kk < 4; ++kk) {
            #pragma unroll
            for (int nn2 = 0; nn2 < 4; ++nn2) {
                uint32_t off = (((nn2 * 2 + (grp >> 1)) * 8 + lr) * KS
                                + kk * 16 + (grp & 1) * 8) * 2;
                uint32_t h0, h1, h2, h3, e0, e1, e2, e3;
                ldsm4(stg + KH_OFF + off, h0, h1, h2, h3);
                ldsm4(stg + KL_OFF + off, e0, e1, e2, e3);
                mma_f16(ca[2 * nn2],     qh[kk][0], qh[kk][1], qh[kk][2], qh[kk][3], h0, h1);
                mma_f16(ca[2 * nn2 + 1], qh[kk][0], qh[kk][1], qh[kk][2], qh[kk][3], h2, h3);
                mma_f16(ca[2 * nn2],     qh[kk][0], qh[kk][1], qh[kk][2], qh[kk][3], e0, e1);
                mma_f16(ca[2 * nn2 + 1], qh[kk][0], qh[kk][1], qh[kk][2], qh[kk][3], e2, e3);
                mma_f16(ca[2 * nn2],     ql[kk][0], ql[kk][1], ql[kk][2], ql[kk][3], h0, h1);
                mma_f16(ca[2 * nn2 + 1], ql[kk][0], ql[kk][1], ql[kk][2], ql[kk][3], h2, h3);
            }
        }
        #pragma unroll
        for (int kk = 0; kk < 4; ++kk) {
            #pragma unroll
            for (int nn2 = 4; nn2 < 8; ++nn2) {
                const int nb = nn2 - 4;
                uint32_t off = (((nn2 * 2 + (grp >> 1)) * 8 + lr) * KS
                                + kk * 16 + (grp & 1) * 8) * 2;
                uint32_t h0, h1, h2, h3, e0, e1, e2, e3;
                ldsm4(stg + KH_OFF + off, h0, h1, h2, h3);
                ldsm4(stg + KL_OFF + off, e0, e1, e2, e3);
                mma_f16(cb[2 * nb],     qh[kk][0], qh[kk][1], qh[kk][2], qh[kk][3], h0, h1);
                mma_f16(cb[2 * nb + 1], qh[kk][0], qh[kk][1], qh[kk][2], qh[kk][3], h2, h3);
                mma_f16(cb[2 * nb],     qh[kk][0], qh[kk][1], qh[kk][2], qh[kk][3], e0, e1);
                mma_f16(cb[2 * nb + 1], qh[kk][0], qh[kk][1], qh[kk][2], qh[kk][3], e2, e3);
                mma_f16(cb[2 * nb],     ql[kk][0], ql[kk][1], ql[kk][2], ql[kk][3], h0, h1);
                mma_f16(cb[2 * nb + 1], ql[kk][0], ql[kk][1], ql[kk][2], ql[kk][3], h2, h3);
            }
        }

        // ---- softmax(A) — overlaps QK(B) drain ----
        {
            float mt0 = -INFINITY, mt1 = -INFINITY;
            #pragma unroll
            for (int nt = 0; nt < 8; ++nt) {
                mt0 = fmaxf(mt0, fmaxf(ca[nt][0], ca[nt][1]));
                mt1 = fmaxf(mt1, fmaxf(ca[nt][2], ca[nt][3]));
            }
            mt0 = fmaxf(mt0, __shfl_xor_sync(0xffffffffu, mt0, 1));
            mt0 = fmaxf(mt0, __shfl_xor_sync(0xffffffffu, mt0, 2));
            mt1 = fmaxf(mt1, __shfl_xor_sync(0xffffffffu, mt1, 1));
            mt1 = fmaxf(mt1, __shfl_xor_sync(0xffffffffu, mt1, 2));

            const float mn0 = fmaxf(m0, mt0);
            const float mn1 = fmaxf(m1, mt1);
            const float sc0 = ex2(m0 - mn0);   // first tile: ex2(-inf) = 0
            const float sc1 = ex2(m1 - mn1);
            m0 = mn0; m1 = mn1;

            uint32_t p[8][2];
            float lp0 = 0.0f, lp1 = 0.0f;
            #pragma unroll
            for (int nt = 0; nt < 8; ++nt) {
                const float e00 = ex2(ca[nt][0] - mn0);
                const float e01 = ex2(ca[nt][1] - mn0);
                const float e10 = ex2(ca[nt][2] - mn1);
                const float e11 = ex2(ca[nt][3] - mn1);
                lp0 += e00 + e01;
                lp1 += e10 + e11;
                __half2 h20 = __floats2half2_rn(e00, e01);
                __half2 h21 = __floats2half2_rn(e10, e11);
                p[nt][0] = *reinterpret_cast<uint32_t*>(&h20);
                p[nt][1] = *reinterpret_cast<uint32_t*>(&h21);
            }
            l0 = l0 * sc0 + lp0;
            l1 = l1 * sc1 + lp1;
            #pragma unroll
            for (int nt = 0; nt < 16; ++nt) {
                o[nt][0] *= sc0; o[nt][1] *= sc0;
                o[nt][2] *= sc1; o[nt][3] *= sc1;
            }

            // ---- PV(A): kv rows 0..63 ----
            #pragma unroll
            for (int kk2 = 0; kk2 < 4; ++kk2) {
                const uint32_t a0 = p[2 * kk2][0];
                const uint32_t a1 = p[2 * kk2][1];
                const uint32_t a2 = p[2 * kk2 + 1][0];
                const uint32_t a3 = p[2 * kk2 + 1][1];
                #pragma unroll
                for (int nn2 = 0; nn2 < 8; ++nn2) {
                    uint32_t va = stg + SV_OFF +
                        ((kk2 * 16 + (grp & 1) * 8 + lr) * VS
                         + (nn2 * 2 + (grp >> 1)) * 8) * 2;
                    uint32_t v0, v1, v2, v3;
                    ldsm4t(va, v0, v1, v2, v3);
                    mma_f16(o[2 * nn2],     a0, a1, a2, a3, v0, v1);
                    mma_f16(o[2 * nn2 + 1], a0, a1, a2, a3, v2, v3);
                }
            }
        }

        // ---- softmax(B) — overlaps PV(A) drain ----
        {
            float mt0 = -INFINITY, mt1 = -INFINITY;
            #pragma unroll
            for (int nt = 0; nt < 8; ++nt) {
                mt0 = fmaxf(mt0, fmaxf(cb[nt][0], cb[nt][1]));
                mt1 = fmaxf(mt1, fmaxf(cb[nt][2], cb[nt][3]));
            }
            mt0 = fmaxf(mt0, __shfl_xor_sync(0xffffffffu, mt0, 1));
            mt0 = fmaxf(mt0, __shfl_xor_sync(0xffffffffu, mt0, 2));
            mt1 = fmaxf(mt1, __shfl_xor_sync(0xffffffffu, mt1, 1));
            mt1 = fmaxf(mt1, __shfl_xor_sync(0xffffffffu, mt1, 2));

            const float mn0 = fmaxf(m0, mt0);
            const float mn1 = fmaxf(m1, mt1);
            const float sc0 = ex2(m0 - mn0);
            const float sc1 = ex2(m1 - mn1);
            m0 = mn0; m1 = mn1;

            uint32_t p[8][2];
            float lp0 = 0.0f, lp1 = 0.0f;
            #pragma unroll
            for (int nt = 0; nt < 8; ++nt) {
                const float e00 = ex2(cb[nt][0] - mn0);
                const float e01 = ex2(cb[nt][1] - mn0);
                const float e10 = ex2(cb[nt][2] - mn1);
                const float e11 = ex2(cb[nt][3] - mn1);
                lp0 += e00 + e01;
                lp1 += e10 + e11;
                __half2 h20 = __floats2half2_rn(e00, e01);
                __half2 h21 = __floats2half2_rn(e10, e11);
                p[nt][0] = *reinterpret_cast<uint32_t*>(&h20);
                p[nt][1] = *reinterpret_cast<uint32_t*>(&h21);
            }
            l0 = l0 * sc0 + lp0;
            l1 = l1 * sc1 + lp1;
            #pragma unroll
            for (int nt = 0; nt < 16; ++nt) {
                o[nt][0] *= sc0; o[nt][1] *= sc0;
                o[nt][2] *= sc1; o[nt][3] *= sc1;
            }

            // ---- PV(B): kv rows 64..127 ----
            #pragma unroll
            for (int kk2 = 4; kk2 < 8; ++kk2) {
                const int kb = kk2 - 4;
                const uint32_t a0 = p[2 * kb][0];
                const uint32_t a1 = p[2 * kb][1];
                const uint32_t a2 = p[2 * kb + 1][0];
                const uint32_t a3 = p[2 * kb + 1][1];
                #pragma unroll
                for (int nn2 = 0; nn2 < 8; ++nn2) {
                    uint32_t va = stg + SV_OFF +
                        ((kk2 * 16 + (grp & 1) * 8 + lr) * VS
                         + (nn2 * 2 + (grp >> 1)) * 8) * 2;
                    uint32_t v0, v1, v2, v3;
                    ldsm4t(va, v0, v1, v2, v3);
                    mma_f16(o[2 * nn2],     a0, a1, a2, a3, v0, v1);
                    mma_f16(o[2 * nn2 + 1], a0, a1, a2, a3, v2, v3);
                }
            }
        }
        __syncthreads();
    }

    l0 += __shfl_xor_sync(0xffffffffu, l0, 1);
    l0 += __shfl_xor_sync(0xffffffffu, l0, 2);
    l1 += __shfl_xor_sync(0xffffffffu, l1, 1);
    l1 += __shfl_xor_sync(0xffffffffu, l1, 2);
    const float inv0 = 1.0f / l0;
    const float inv1 = 1.0f / l1;

    #pragma unroll
    for (int nt = 0; nt < 16; ++nt) {
        float2 w0 = make_float2(o[nt][0] * inv0, o[nt][1] * inv0);
        float2 w1 = make_float2(o[nt][2] * inv1, o[nt][3] * inv1);
        *reinterpret_cast<float2*>(&outb[(size_t)(wbase + g) * FDIM + nt * 8 + 2 * tig]) = w0;
        *reinterpret_cast<float2*>(&outb[(size_t)(wbase + g + 8) * FDIM + nt * 8 + 2 * tig]) = w1;
    }
}

// ---------------------------------------------------------------------------
// One-shot weight prep: transpose + hi/lo-split the three weight matrices
// into device globals. grid = 256 CTAs (n-row each), 128 threads (k).
// n 0..63 -> wk, 64..127 -> wq, 128..255 -> wv.
// ---------------------------------------------------------------------------
__global__ __launch_bounds__(128) void wprep_kernel(
    const float* __restrict__ wk,
    const float* __restrict__ wq,
    const float* __restrict__ wv,
    __half* __restrict__ WKh, __half* __restrict__ WKl,
    __half* __restrict__ WQh, __half* __restrict__ WQl,
    __half* __restrict__ WVh) {
    const int n = blockIdx.x;
    const int k = threadIdx.x;
    if (n < 64) {
        float v = wk[(size_t)k * 64 + n];
        __half hi = __float2half_rn(v);
        WKh[(size_t)n * 128 + k] = hi;
        WKl[(size_t)n * 128 + k] = __float2half_rn(v - __half2float(hi));
    } else if (n < 128) {
        float v = wq[(size_t)k * 64 + (n - 64)];
        __half hi = __float2half_rn(v);
        WQh[(size_t)(n - 64) * 128 + k] = hi;
        WQl[(size_t)(n - 64) * 128 + k] = __float2half_rn(v - __half2float(hi));
    } else {
        float v = wv[(size_t)k * 128 + (n - 128)];
        WVh[(size_t)(n - 128) * 128 + k] = __float2half_rn(v);
    }
}

// ---------------------------------------------------------------------------
// Tensor-core projections: x tile split hi/lo once; pre-transposed weights
// pulled into smem via cp.async (no per-CTA transpose work).
// grid = (MROWS/128, 1), 256 threads. K,Q: 3-term compensated product,
// hi/lo outputs (Q scaled by log2e). V: 2-term (x hi+lo, w hi), fp16 output.
// ---------------------------------------------------------------------------
#define PXS 136                                  // half stride (272 B rows)
#define PXH_OFF 0
#define PXL_OFF 34816
#define WKH_OFF 69632
#define WKL_OFF (WKH_OFF + 17408)                // 87040
#define WQH_OFF (WKL_OFF + 17408)                // 104448
#define WQL_OFF (WQH_OFF + 17408)                // 121856
#define WVH_OFF (WQL_OFF + 17408)                // 139264
#define PROJ_SMEM (WVH_OFF + 34816)              // 174080

__global__ __launch_bounds__(256, 1) void proj_mma_kernel(
    const float* __restrict__ x,
    const __half* __restrict__ WKh, const __half* __restrict__ WKl,
    const __half* __restrict__ WQh, const __half* __restrict__ WQl,
    const __half* __restrict__ WVh,
    __half* __restrict__ Kh, __half* __restrict__ Kl,
    __half* __restrict__ Qh, __half* __restrict__ Ql,
    __half* __restrict__ Vh) {
    extern __shared__ char ps[];
    const uint32_t sb = cvta_s(ps);
    const int tid = threadIdx.x;
    const int lane = tid & 31;
    const int g = lane >> 2;
    const int tig = lane & 3;
    const int grp = lane >> 3;
    const int lr = lane & 7;
    const int wbase = (tid >> 5) * 16;
    const int row0 = blockIdx.x * 128;

    // cp.async all weight tiles into padded smem (coalesced 16B chunks)
    #pragma unroll
    for (int i = 0; i < 4; ++i) {
        int c = i * 256 + tid;            // 0..1023 over 64 rows x 16 chunks
        int r = c >> 4, c8 = (c & 15) * 8;
        cpa16(sb + WKH_OFF + (r * PXS + c8) * 2, WKh + (size_t)r * 128 + c8);
        cpa16(sb + WKL_OFF + (r * PXS + c8) * 2, WKl + (size_t)r * 128 + c8);
        cpa16(sb + WQH_OFF + (r * PXS + c8) * 2, WQh + (size_t)r * 128 + c8);
        cpa16(sb + WQL_OFF + (r * PXS + c8) * 2, WQl + (size_t)r * 128 + c8);
    }
    #pragma unroll
    for (int i = 0; i < 8; ++i) {
        int c = i * 256 + tid;            // 0..2047 over 128 rows x 16 chunks
        int r = c >> 4, c8 = (c & 15) * 8;
        cpa16(sb + WVH_OFF + (r * PXS + c8) * 2, WVh + (size_t)r * 128 + c8);
    }
    CP_COMMIT();

    // Load + split x tile [128][128] fp32 -> hi/lo fp16 (overlaps cp.async)
    #pragma unroll
    for (int i = 0; i < 16; ++i) {
        int e = i * 256 + tid;
        int r = e >> 5;
        int c4 = (e & 31) * 4;
        float4 v = *reinterpret_cast<const float4*>(&x[(size_t)(row0 + r) * 128 + c4]);
        __half hx = __float2half_rn(v.x), hy = __float2half_rn(v.y);
        __half hz = __float2half_rn(v.z), hw = __float2half_rn(v.w);
        char* dh = ps + PXH_OFF + ((size_t)r * PXS + c4) * 2;
        char* dl = ps + PXL_OFF + ((size_t)r * PXS + c4) * 2;
        *reinterpret_cast<__half2*>(dh)     = __halves2half2(hx, hy);
        *reinterpret_cast<__half2*>(dh + 4) = __halves2half2(hz, hw);
        *reinterpret_cast<__half2*>(dl) = __halves2half2(
            __float2half_rn(v.x - __half2float(hx)),
            __float2half_rn(v.y - __half2float(hy)));
        *reinterpret_cast<__half2*>(dl + 4) = __halves2half2(
            __float2half_rn(v.z - __half2float(hz)),
            __float2half_rn(v.w - __half2float(hw)));
    }
    CP_WAIT0();
    __syncthreads();

    // A-frags (x hi/lo), 8 k-steps — held for all three GEMMs
    uint32_t ah[8][4], al[8][4];
    #pragma unroll
    for (int kk = 0; kk < 8; ++kk) {
        uint32_t a = sb + PXH_OFF +
            ((wbase + lr + (grp & 1) * 8) * PXS + kk * 16 + (grp >> 1) * 8) * 2;
        ldsm4(a, ah[kk][0], ah[kk][1], ah[kk][2], ah[kk][3]);
        ldsm4(a + (PXL_OFF - PXH_OFF), al[kk][0], al[kk][1], al[kk][2], al[kk][3]);
    }

    // ---- K and Q: N=64, 3-term compensated product ----
    #pragma unroll
    for (int which = 0; which < 2; ++which) {
        const uint32_t wh_off = (which == 0) ? WKH_OFF : WQH_OFF;
        const uint32_t wl_off = (which == 0) ? WKL_OFF : WQL_OFF;

        float c[8][4];
        #pragma unroll
        for (int nt = 0; nt < 8; ++nt)
            #pragma unroll
            for (int j = 0; j < 4; ++j) c[nt][j] = 0.0f;

        #pragma unroll
        for (int kk = 0; kk < 8; ++kk) {
            #pragma unroll
            for (int nn2 = 0; nn2 < 4; ++nn2) {
                uint32_t off = (((nn2 * 2 + (grp >> 1)) * 8 + lr) * PXS
                                + kk * 16 + (grp & 1) * 8) * 2;
                uint32_t h0, h1, h2, h3, e0, e1, e2, e3;
                ldsm4(sb + wh_off + off, h0, h1, h2, h3);
                ldsm4(sb + wl_off + off, e0, e1, e2, e3);
                mma_f16(c[2 * nn2],     ah[kk][0], ah[kk][1], ah[kk][2], ah[kk][3], h0, h1);
                mma_f16(c[2 * nn2 + 1], ah[kk][0], ah[kk][1], ah[kk][2], ah[kk][3], h2, h3);
                mma_f16(c[2 * nn2],     ah[kk][0], ah[kk][1], ah[kk][2], ah[kk][3], e0, e1);
                mma_f16(c[2 * nn2 + 1], ah[kk][0], ah[kk][1], ah[kk][2], ah[kk][3], e2, e3);
                mma_f16(c[2 * nn2],     al[kk][0], al[kk][1], al[kk][2], al[kk][3], h0, h1);
                mma_f16(c[2 * nn2 + 1], al[kk][0], al[kk][1], al[kk][2], al[kk][3], h2, h3);
            }
        }

        const float scale = (which == 1) ? LOG2E : 1.0f;  // fold log2e into Q
        __half* Hh = (which == 0) ? Kh : Qh;
        __half* Hl = (which == 0) ? Kl : Ql;
        #pragma unroll
        for (int nt = 0; nt < 8; ++nt) {
            const int col = nt * 8 + 2 * tig;
            #pragma unroll
            for (int half_m = 0; half_m < 2; ++half_m) {
                const size_t idx =
                    (size_t)(row0 + wbase + g + half_m * 8) * WDIM + col;
                const float v0 = c[nt][2 * half_m] * scale;
                const float v1 = c[nt][2 * half_m + 1] * scale;
                const __half h0 = __float2half_rn(v0);
                const __half h1 = __float2half_rn(v1);
                *reinterpret_cast<__half2*>(&Hh[idx]) = __halves2half2(h0, h1);
                *reinterpret_cast<__half2*>(&Hl[idx]) = __halves2half2(
                    __float2half_rn(v0 - __half2float(h0)),
                    __float2half_rn(v1 - __half2float(h1)));
            }
        }
    }

    // ---- V: N=128, 2-term (x hi+lo, w hi) ----
    {
        float c[16][4];
        #pragma unroll
        for (int nt = 0; nt < 16; ++nt)
            #pragma unroll
            for (int j = 0; j < 4; ++j) c[nt][j] = 0.0f;

        #pragma unroll
        for (int kk = 0; kk < 8; ++kk) {
            #pragma unroll
            for (int nn2 = 0; nn2 < 8; ++nn2) {
                uint32_t off = (((nn2 * 2 + (grp >> 1)) * 8 + lr) * PXS
                                + kk * 16 + (grp & 1) * 8) * 2;
                uint32_t h0, h1, h2, h3;
                ldsm4(sb + WVH_OFF + off, h0, h1, h2, h3);
                mma_f16(c[2 * nn2],     ah[kk][0], ah[kk][1], ah[kk][2], ah[kk][3], h0, h1);
                mma_f16(c[2 * nn2 + 1], ah[kk][0], ah[kk][1], ah[kk][2], ah[kk][3], h2, h3);
                mma_f16(c[2 * nn2],     al[kk][0], al[kk][1], al[kk][2], al[kk][3], h0, h1);
                mma_f16(c[2 * nn2 + 1], al[kk][0], al[kk][1], al[kk][2], al[kk][3], h2, h3);
            }
        }

        #pragma unroll
        for (int nt = 0; nt < 16; ++nt) {
            const int col = nt * 8 + 2 * tig;
            #pragma unroll
            for (int half_m = 0; half_m < 2; ++half_m) {
                const size_t idx =
                    (size_t)(row0 + wbase + g + half_m * 8) * FDIM + col;
                *reinterpret_cast<__half2*>(&Vh[idx]) = __halves2half2(
                    __float2half_rn(c[nt][2 * half_m]),
                    __float2half_rn(c[nt][2 * half_m + 1]));
            }
        }
    }
}

// ---------------------------------------------------------------------------
extern "C" void kernel_launch(void* const* d_in, const int* in_sizes, int n_in,
                              void* d_out, int out_size) {
    const float* x  = (const float*)d_in[0];
    // d_in[1] = adj (bool), unused by the reference math
    const float* wk = (const float*)d_in[2];
    const float* wv = (const float*)d_in[3];
    const float* wq = (const float*)d_in[4];
    float* out = (float*)d_out;

    void *pQh, *pQl, *pKh, *pKl, *pVh;
    void *pWKh, *pWKl, *pWQh, *pWQl, *pWVh;
    cudaGetSymbolAddress(&pQh, g_Qh);
    cudaGetSymbolAddress(&pQl, g_Ql);
    cudaGetSymbolAddress(&pKh, g_Kh);
    cudaGetSymbolAddress(&pKl, g_Kl);
    cudaGetSymbolAddress(&pVh, g_Vh);
    cudaGetSymbolAddress(&pWKh, g_WKh);
    cudaGetSymbolAddress(&pWKl, g_WKl);
    cudaGetSymbolAddress(&pWQh, g_WQh);
    cudaGetSymbolAddress(&pWQl, g_WQl);
    cudaGetSymbolAddress(&pWVh, g_WVh);

    cudaFuncSetAttribute(attn_mma_kernel,
                         cudaFuncAttributeMaxDynamicSharedMemorySize, ATTN_SMEM);
    cudaFuncSetAttribute(proj_mma_kernel,
                         cudaFuncAttributeMaxDynamicSharedMemorySize, PROJ_SMEM);

    wprep_kernel<<<256, 128>>>(
        wk, wq, wv,
        (__half*)pWKh, (__half*)pWKl, (__half*)pWQh, (__half*)pWQl,
        (__half*)pWVh);

    proj_mma_kernel<<<dim3(MROWS / 128, 1), 256, PROJ_SMEM>>>(
        x,
        (const __half*)pWKh, (const __half*)pWKl,
        (const __half*)pWQh, (const __half*)pWQl,
        (const __half*)pWVh,
        (__half*)pKh, (__half*)pKl, (__half*)pQh, (__half*)pQl, (__half*)pVh);

    attn_mma_kernel<<<dim3(SEQ / 128, BATCH), 256, ATTN_SMEM>>>(
        (const __half*)pQh, (const __half*)pQl,
        (const __half*)pKh, (const __half*)pKl,
        (const __half*)pVh, out);
}